// round 4
// baseline (speedup 1.0000x reference)
#include <cuda_runtime.h>
#include <cuda_bf16.h>
#include <math.h>
#include <stdint.h>

// ---------------- problem constants ----------------
#define QN      40000
#define NCAM    6
#define IMGW    480.0f
#define IMGH    224.0f

// level geometry
#define HW0 6720
#define HW1 1680
#define HW2 420
#define HW3 105
#define TOTPIX 8925

// scratch buffers
__device__ float g_tf[(size_t)TOTPIX * NCAM * 128];          // 27.4 MB transposed features
__device__ float g_fvec[(size_t)QN * 1024];                   // 163.8 MB
__device__ float g_h1[(size_t)QN * 512];                      // 81.9 MB
__device__ float g_h2[(size_t)QN * 512];                      // 81.9 MB
__device__ float g_w1[1024 * 512];                            // tf32-rounded weights
__device__ float g_w2[512 * 512];
__device__ float g_w3[512 * 512];
__device__ float g_w4[512 * 128];

__device__ __forceinline__ uint32_t f2tf(float x) {
    uint32_t u;
    asm("cvt.rna.tf32.f32 %0, %1;" : "=r"(u) : "f"(x));
    return u;
}
__device__ __forceinline__ float rnatf(float x) {
    return __uint_as_float(f2tf(x));
}
__device__ __forceinline__ void cp16(uint32_t dst, const void* src, bool ok) {
    int sz = ok ? 16 : 0;
    asm volatile("cp.async.cg.shared.global [%0], [%1], 16, %2;"
                 :: "r"(dst), "l"(src), "r"(sz));
}

// ---------------- tf32 round weights ----------------
__global__ void round_tf32_kernel(const float* __restrict__ in, float* __restrict__ out, int n) {
    int i = blockIdx.x * 256 + threadIdx.x;
    if (i < n) out[i] = rnatf(in[i]);
}

// ---------------- feat transpose: [n][128ch][HW] -> [n][HW][128] ----------------
__global__ void transpose_feat_kernel(const float* __restrict__ feat,
                                      float* __restrict__ dst, int HW) {
    __shared__ float s[32][33];
    int n    = blockIdx.z;
    int ch0  = blockIdx.y * 32;
    int pix0 = blockIdx.x * 32;
    int tx = threadIdx.x, ty = threadIdx.y;

    int pix = pix0 + tx;
    int ch  = ch0 + ty;
    if (pix < HW)
        s[ty][tx] = feat[((size_t)(n * 128 + ch)) * HW + pix];
    __syncthreads();
    int pixw = pix0 + ty;
    int chw  = ch0 + tx;
    if (pixw < HW)
        dst[((size_t)n * HW + pixw) * 128 + chw] = s[tx][ty];
}

// ---------------- sampling + scale softmax + projection ----------------
__global__ __launch_bounds__(128) void sample_kernel(
    const float* __restrict__ query,   // [Q][P][128]
    const float* __restrict__ qpos,    // [Z=8][Q][3]
    const float* __restrict__ l2i,     // [6][4][4]
    const float* __restrict__ Wsw,     // [128][16]
    const float* __restrict__ bsw)     // [16]
{
    __shared__ __align__(16) float s_q[1024];
    __shared__ __align__(16) float s_wsw[2048];
    __shared__ float s_logit[128];
    __shared__ float s_sw[128];
    __shared__ float s_bsw[16];
    __shared__ float s_l2i[96];
    __shared__ float s_qp[8][3];
    __shared__ float s_u[8], s_v[8];
    __shared__ int   s_cam[8], s_ok[8];

    const int q   = blockIdx.x;
    const int tid = threadIdx.x;

    {
        const float4* qv = (const float4*)(query + (size_t)q * 1024);
        float4* d = (float4*)s_q;
        d[tid] = qv[tid]; d[tid + 128] = qv[tid + 128];

        const float4* wv = (const float4*)Wsw;
        float4* sw4 = (float4*)s_wsw;
        sw4[tid] = wv[tid]; sw4[tid + 128] = wv[tid + 128];
        sw4[tid + 256] = wv[tid + 256]; sw4[tid + 384] = wv[tid + 384];

        if (tid < 16) s_bsw[tid] = bsw[tid];
        if (tid < 96) s_l2i[tid] = l2i[tid];
        if (tid < 24) s_qp[tid / 3][tid % 3] = qpos[((size_t)(tid / 3) * QN + q) * 3 + (tid % 3)];
    }
    __syncthreads();

    // scale-weight logits
    {
        int p = tid >> 4, gl = tid & 15;
        float acc = s_bsw[gl];
        const float* qrow = s_q + p * 128;
        #pragma unroll 8
        for (int k = 0; k < 128; k++) acc += qrow[k] * s_wsw[k * 16 + gl];
        s_logit[tid] = acc;
    }
    // projection: first valid camera per point
    if (tid < 8) {
        int p = tid;
        float X = s_qp[p][0] * 100.f - 50.f;
        float Y = s_qp[p][1] * 100.f - 50.f;
        float Zc = s_qp[p][2] * 8.f - 4.f;
        int found = 0, cam = 0; float uu = 0.f, vv = 0.f;
        #pragma unroll
        for (int n = 0; n < 6; n++) {
            const float* M = s_l2i + n * 16;
            float c0 = M[0] * X + M[1] * Y + M[2]  * Zc + M[3];
            float c1 = M[4] * X + M[5] * Y + M[6]  * Zc + M[7];
            float c2 = M[8] * X + M[9] * Y + M[10] * Zc + M[11];
            float den = fmaxf(c2, 1e-6f);
            float u = (c0 / den) / IMGW;
            float v = (c1 / den) / IMGH;
            bool val = (c2 > 1e-6f) && (u > 0.f) && (u < 1.f) && (v > 0.f) && (v < 1.f);
            if (val && !found) { found = 1; cam = n; uu = u; vv = v; }
        }
        s_cam[p] = cam; s_ok[p] = found; s_u[p] = uu; s_v[p] = vv;
    }
    __syncthreads();

    // softmax over levels per (p,g)
    if (tid < 32) {
        int base = tid * 4;
        float a = s_logit[base], b = s_logit[base + 1], c = s_logit[base + 2], d = s_logit[base + 3];
        float m = fmaxf(fmaxf(a, b), fmaxf(c, d));
        float ea = expf(a - m), eb = expf(b - m), ec = expf(c - m), ed = expf(d - m);
        float inv = 1.f / (ea + eb + ec + ed);
        s_sw[base] = ea * inv; s_sw[base + 1] = eb * inv;
        s_sw[base + 2] = ec * inv; s_sw[base + 3] = ed * inv;
    }
    __syncthreads();

    const int cch = tid;
    const int LW[4]    = {120, 60, 30, 15};
    const int LH[4]    = {56, 28, 14, 7};
    const int LHW[4]   = {HW0, HW1, HW2, HW3};
    const int LBASE[4] = {0, HW0 * NCAM * 128, (HW0 + HW1) * NCAM * 128, (HW0 + HW1 + HW2) * NCAM * 128};

    const int g = cch >> 5;
    float* outp = g_fvec + (size_t)q * 1024 + cch;

    #pragma unroll 1
    for (int p = 0; p < 8; p++) {
        float sval = 0.f;
        if (s_ok[p]) {
            int cam = s_cam[p];
            float u = s_u[p], v = s_v[p];
            const float* swp = s_sw + p * 16 + g * 4;
            #pragma unroll
            for (int l = 0; l < 4; l++) {
                int w = LW[l], h = LH[l];
                const float* base = g_tf + LBASE[l] + (size_t)cam * LHW[l] * 128;
                float x = u * (float)w - 0.5f;
                float y = v * (float)h - 0.5f;
                float xf = floorf(x), yf = floorf(y);
                float wx = x - xf, wy = y - yf;
                int x0 = (int)xf, y0 = (int)yf;
                int x1 = x0 + 1, y1 = y0 + 1;
                bool ix0 = (x0 >= 0) && (x0 < w);
                bool ix1 = (x1 < w);
                bool iy0 = (y0 >= 0) && (y0 < h);
                bool iy1 = (y1 < h);
                float v00 = (iy0 && ix0) ? base[((size_t)y0 * w + x0) * 128 + cch] : 0.f;
                float v01 = (iy0 && ix1) ? base[((size_t)y0 * w + x1) * 128 + cch] : 0.f;
                float v10 = (iy1 && ix0) ? base[((size_t)y1 * w + x0) * 128 + cch] : 0.f;
                float v11 = (iy1 && ix1) ? base[((size_t)y1 * w + x1) * 128 + cch] : 0.f;
                float bil = v00 * (1.f - wx) * (1.f - wy) + v01 * wx * (1.f - wy)
                          + v10 * (1.f - wx) * wy + v11 * wx * wy;
                sval += bil * swp[l];
            }
        }
        outp[p * 128] = sval;
    }
}

// ---------------- tf32 GEMM v2: cp.async double-buffered, 256x128 block ----------------
// A and W must already be tf32-rounded (rna). grid = (N/128, ceil(M/256)).
// C = act(A@W + bias), optionally rna-rounded on store.
#define ASZ (256 * 36)
#define BSZ (32 * 136)
#define STG (ASZ + BSZ)

template <int RELU, int ROUND>
__global__ __launch_bounds__(256, 1) void mma_gemm2(
    const float* __restrict__ A, const float* __restrict__ W,
    const float* __restrict__ bias, float* __restrict__ C,
    int M, int K, int N)
{
    extern __shared__ uint32_t sm[];

    const int tid  = threadIdx.x;
    const int lane = tid & 31;
    const int warp = tid >> 5;
    const int wm = warp >> 1;          // 0..3 (64 rows each)
    const int wn = warp & 1;           // 0..1 (64 cols each)
    const int bn = blockIdx.x * 128, bm = blockIdx.y * 256;

    float c[4][8][4];
    #pragma unroll
    for (int i = 0; i < 4; i++)
        #pragma unroll
        for (int j = 0; j < 8; j++) {
            c[i][j][0] = 0.f; c[i][j][1] = 0.f; c[i][j][2] = 0.f; c[i][j][3] = 0.f;
        }

    // cp.async slab loader
    const int arow = tid >> 3, akq = tid & 7;    // A: +32 rows per i (8 iters)
    const int bkr  = tid >> 5, bnq = tid & 31;   // B: +8 k-rows per i (4 iters)

    uint32_t as_base[2], bs_base[2];
    #pragma unroll
    for (int s = 0; s < 2; s++) {
        as_base[s] = (uint32_t)__cvta_generic_to_shared(sm + s * STG);
        bs_base[s] = (uint32_t)__cvta_generic_to_shared(sm + s * STG + ASZ);
    }

    auto load_slab = [&](int k0, int s) {
        #pragma unroll
        for (int i = 0; i < 8; i++) {
            int row = arow + 32 * i;
            bool ok = (bm + row) < M;
            const float* src = A + (size_t)(bm + (ok ? row : 0)) * K + k0 + akq * 4;
            cp16(as_base[s] + (row * 36 + akq * 4) * 4, src, ok);
        }
        #pragma unroll
        for (int i = 0; i < 4; i++) {
            int kr = bkr + 8 * i;
            const float* src = W + (size_t)(k0 + kr) * N + bn + bnq * 4;
            cp16(bs_base[s] + (kr * 136 + bnq * 4) * 4, src, true);
        }
    };

    load_slab(0, 0);
    asm volatile("cp.async.commit_group;");

    for (int k0 = 0, s = 0; k0 < K; k0 += 32, s ^= 1) {
        if (k0 + 32 < K) load_slab(k0 + 32, s ^ 1);
        asm volatile("cp.async.commit_group;");
        asm volatile("cp.async.wait_group 1;");
        __syncthreads();

        const uint32_t* As = sm + s * STG;
        const uint32_t* Bs = sm + s * STG + ASZ;

        #pragma unroll
        for (int kt = 0; kt < 4; kt++) {
            const int kk = kt * 8 + (lane & 3);
            uint32_t a[4][4], b[8][2];
            const int mrow = wm * 64 + (lane >> 2);
            #pragma unroll
            for (int mt = 0; mt < 4; mt++) {
                int m = mrow + mt * 16;
                a[mt][0] = As[m * 36 + kk];
                a[mt][1] = As[(m + 8) * 36 + kk];
                a[mt][2] = As[m * 36 + kk + 4];
                a[mt][3] = As[(m + 8) * 36 + kk + 4];
            }
            const int nc = wn * 64 + (lane >> 2);
            #pragma unroll
            for (int nt = 0; nt < 8; nt++) {
                int n = nc + nt * 8;
                b[nt][0] = Bs[kk * 136 + n];
                b[nt][1] = Bs[(kk + 4) * 136 + n];
            }
            #pragma unroll
            for (int mt = 0; mt < 4; mt++)
                #pragma unroll
                for (int nt = 0; nt < 8; nt++) {
                    asm volatile(
                        "mma.sync.aligned.m16n8k8.row.col.f32.tf32.tf32.f32 "
                        "{%0,%1,%2,%3}, {%4,%5,%6,%7}, {%8,%9}, {%0,%1,%2,%3};"
                        : "+f"(c[mt][nt][0]), "+f"(c[mt][nt][1]),
                          "+f"(c[mt][nt][2]), "+f"(c[mt][nt][3])
                        : "r"(a[mt][0]), "r"(a[mt][1]), "r"(a[mt][2]), "r"(a[mt][3]),
                          "r"(b[nt][0]), "r"(b[nt][1]));
                }
        }
        __syncthreads();
    }

    #pragma unroll
    for (int mt = 0; mt < 4; mt++) {
        int row0 = bm + wm * 64 + mt * 16 + (lane >> 2);
        #pragma unroll
        for (int nt = 0; nt < 8; nt++) {
            int col = bn + wn * 64 + nt * 8 + (lane & 3) * 2;
            float b0 = bias[col], b1 = bias[col + 1];
            #pragma unroll
            for (int half = 0; half < 2; half++) {
                int row = row0 + half * 8;
                if (row < M) {
                    float v0 = c[mt][nt][half * 2 + 0] + b0;
                    float v1 = c[mt][nt][half * 2 + 1] + b1;
                    if (RELU)  { v0 = fmaxf(v0, 0.f); v1 = fmaxf(v1, 0.f); }
                    if (ROUND) { v0 = rnatf(v0); v1 = rnatf(v1); }
                    float* cp = C + (size_t)row * N + col;
                    cp[0] = v0; cp[1] = v1;
                }
            }
        }
    }
}

// ---------------- fused positional-encoding GEMM ----------------
// fvec[r,col] = rna(fvec[r,col] + relu(qp[r]@pe_w1+pe_b1) @ pe_w2 + pe_b2)
__global__ __launch_bounds__(256, 2) void pe_gemm(
    const float* __restrict__ qpos,    // [8][Q][3]
    const float* __restrict__ pew1,    // [3][256]
    const float* __restrict__ peb1,    // [256]
    const float* __restrict__ pew2,    // [256][128]
    const float* __restrict__ peb2,    // [128]
    float* __restrict__ C)             // fvec
{
    __shared__ uint32_t As[128 * 36];
    __shared__ uint32_t Bs[32 * 136];
    __shared__ float sw1[768];
    __shared__ float sb1[256];
    __shared__ float sxyz[128 * 3];

    const int tid  = threadIdx.x;
    const int lane = tid & 31;
    const int warp = tid >> 5;
    const int wm = warp >> 2;
    const int wn = warp & 3;
    const int bm = blockIdx.x * 128;

    sw1[tid] = pew1[tid]; sw1[tid + 256] = pew1[tid + 256]; sw1[tid + 512] = pew1[tid + 512];
    if (tid < 256) sb1[tid] = peb1[tid];
    if (tid < 128) {
        int r = bm + tid;
        int q = r >> 3, p = r & 7;
        const float* xp = qpos + ((size_t)p * QN + q) * 3;
        sxyz[tid * 3 + 0] = xp[0];
        sxyz[tid * 3 + 1] = xp[1];
        sxyz[tid * 3 + 2] = xp[2];
    }

    float c[4][4][4];
    #pragma unroll
    for (int i = 0; i < 4; i++)
        #pragma unroll
        for (int j = 0; j < 4; j++) {
            c[i][j][0] = 0.f; c[i][j][1] = 0.f; c[i][j][2] = 0.f; c[i][j][3] = 0.f;
        }

    const int am = tid >> 3, akq = tid & 7;
    const int bkr = tid >> 5, bnq = tid & 31;

    __syncthreads();

    for (int k0 = 0; k0 < 256; k0 += 32) {
        __syncthreads();
        #pragma unroll
        for (int i = 0; i < 4; i++) {
            int m = am + 32 * i;
            float x0 = sxyz[m * 3], x1 = sxyz[m * 3 + 1], x2 = sxyz[m * 3 + 2];
            uint32_t* p = &As[m * 36 + akq * 4];
            #pragma unroll
            for (int t = 0; t < 4; t++) {
                int j = k0 + akq * 4 + t;
                float h = sb1[j] + x0 * sw1[j] + x1 * sw1[256 + j] + x2 * sw1[512 + j];
                p[t] = f2tf(fmaxf(h, 0.f));
            }
        }
        #pragma unroll
        for (int i = 0; i < 4; i++) {
            float4 b4 = *(const float4*)(pew2 + (size_t)(k0 + bkr + 8 * i) * 128 + bnq * 4);
            uint32_t* p = &Bs[(bkr + 8 * i) * 136 + bnq * 4];
            p[0] = f2tf(b4.x); p[1] = f2tf(b4.y); p[2] = f2tf(b4.z); p[3] = f2tf(b4.w);
        }
        __syncthreads();

        #pragma unroll
        for (int kt = 0; kt < 4; kt++) {
            const int kk = kt * 8 + (lane & 3);
            uint32_t a[4][4], b[4][2];
            const int mrow = wm * 64 + (lane >> 2);
            #pragma unroll
            for (int mt = 0; mt < 4; mt++) {
                int m = mrow + mt * 16;
                a[mt][0] = As[m * 36 + kk];
                a[mt][1] = As[(m + 8) * 36 + kk];
                a[mt][2] = As[m * 36 + kk + 4];
                a[mt][3] = As[(m + 8) * 36 + kk + 4];
            }
            const int ncol = wn * 32 + (lane >> 2);
            #pragma unroll
            for (int nt = 0; nt < 4; nt++) {
                int n = ncol + nt * 8;
                b[nt][0] = Bs[kk * 136 + n];
                b[nt][1] = Bs[(kk + 4) * 136 + n];
            }
            #pragma unroll
            for (int mt = 0; mt < 4; mt++)
                #pragma unroll
                for (int nt = 0; nt < 4; nt++) {
                    asm volatile(
                        "mma.sync.aligned.m16n8k8.row.col.f32.tf32.tf32.f32 "
                        "{%0,%1,%2,%3}, {%4,%5,%6,%7}, {%8,%9}, {%0,%1,%2,%3};"
                        : "+f"(c[mt][nt][0]), "+f"(c[mt][nt][1]),
                          "+f"(c[mt][nt][2]), "+f"(c[mt][nt][3])
                        : "r"(a[mt][0]), "r"(a[mt][1]), "r"(a[mt][2]), "r"(a[mt][3]),
                          "r"(b[nt][0]), "r"(b[nt][1]));
                }
        }
    }

    #pragma unroll
    for (int mt = 0; mt < 4; mt++) {
        int row0 = bm + wm * 64 + mt * 16 + (lane >> 2);
        #pragma unroll
        for (int nt = 0; nt < 4; nt++) {
            int col = wn * 32 + nt * 8 + (lane & 3) * 2;
            float b0 = peb2[col], b1 = peb2[col + 1];
            #pragma unroll
            for (int half = 0; half < 2; half++) {
                int row = row0 + half * 8;
                float* cp = C + (size_t)row * 128 + col;
                cp[0] = rnatf(cp[0] + c[mt][nt][half * 2 + 0] + b0);
                cp[1] = rnatf(cp[1] + c[mt][nt][half * 2 + 1] + b1);
            }
        }
    }
}

// ---------------- final transpose: [Q][128] -> [128][Q] ----------------
__global__ void transpose_out_kernel(const float* __restrict__ in, float* __restrict__ out) {
    __shared__ float s[32][33];
    int q0 = blockIdx.x * 32, e0 = blockIdx.y * 32;
    int tx = threadIdx.x, ty = threadIdx.y;
    s[ty][tx] = in[(size_t)(q0 + ty) * 128 + (e0 + tx)];
    __syncthreads();
    out[(size_t)(e0 + ty) * QN + (q0 + tx)] = s[tx][ty];
}

// ---------------- launch ----------------
extern "C" void kernel_launch(void* const* d_in, const int* in_sizes, int n_in,
                              void* d_out, int out_size) {
    const float* feat0 = (const float*)d_in[0];
    const float* feat1 = (const float*)d_in[1];
    const float* feat2 = (const float*)d_in[2];
    const float* feat3 = (const float*)d_in[3];
    const float* query = (const float*)d_in[4];
    const float* qpos  = (const float*)d_in[5];
    const float* l2i   = (const float*)d_in[6];
    const float* Wsw   = (const float*)d_in[7];
    const float* bsw   = (const float*)d_in[8];
    const float* pew1  = (const float*)d_in[9];
    const float* peb1  = (const float*)d_in[10];
    const float* pew2  = (const float*)d_in[11];
    const float* peb2  = (const float*)d_in[12];
    const float* cw1   = (const float*)d_in[13];
    const float* cb1   = (const float*)d_in[14];
    const float* cw2   = (const float*)d_in[15];
    const float* cb2   = (const float*)d_in[16];
    const float* cw3   = (const float*)d_in[17];
    const float* cb3   = (const float*)d_in[18];
    const float* cw4   = (const float*)d_in[19];
    const float* cb4   = (const float*)d_in[20];
    float* out = (float*)d_out;

    float* tf;  cudaGetSymbolAddress((void**)&tf,  g_tf);
    float* fv;  cudaGetSymbolAddress((void**)&fv,  g_fvec);
    float* h1;  cudaGetSymbolAddress((void**)&h1,  g_h1);
    float* h2;  cudaGetSymbolAddress((void**)&h2,  g_h2);
    float* w1;  cudaGetSymbolAddress((void**)&w1,  g_w1);
    float* w2;  cudaGetSymbolAddress((void**)&w2,  g_w2);
    float* w3;  cudaGetSymbolAddress((void**)&w3,  g_w3);
    float* w4;  cudaGetSymbolAddress((void**)&w4,  g_w4);

    static int smem_set = 0;
    if (!smem_set) {
        cudaFuncSetAttribute(mma_gemm2<1, 1>, cudaFuncAttributeMaxDynamicSharedMemorySize, STG * 2 * 4);
        cudaFuncSetAttribute(mma_gemm2<0, 0>, cudaFuncAttributeMaxDynamicSharedMemorySize, STG * 2 * 4);
        smem_set = 1;
    }

    dim3 tb(32, 32);
    transpose_feat_kernel<<<dim3((HW0 + 31) / 32, 4, 6), tb>>>(feat0, tf, HW0);
    transpose_feat_kernel<<<dim3((HW1 + 31) / 32, 4, 6), tb>>>(feat1, tf + (size_t)HW0 * NCAM * 128, HW1);
    transpose_feat_kernel<<<dim3((HW2 + 31) / 32, 4, 6), tb>>>(feat2, tf + (size_t)(HW0 + HW1) * NCAM * 128, HW2);
    transpose_feat_kernel<<<dim3((HW3 + 31) / 32, 4, 6), tb>>>(feat3, tf + (size_t)(HW0 + HW1 + HW2) * NCAM * 128, HW3);

    round_tf32_kernel<<<(1024 * 512 + 255) / 256, 256>>>(cw1, w1, 1024 * 512);
    round_tf32_kernel<<<(512 * 512 + 255) / 256, 256>>>(cw2, w2, 512 * 512);
    round_tf32_kernel<<<(512 * 512 + 255) / 256, 256>>>(cw3, w3, 512 * 512);
    round_tf32_kernel<<<(512 * 128 + 255) / 256, 256>>>(cw4, w4, 512 * 128);

    sample_kernel<<<QN, 128>>>(query, qpos, l2i, Wsw, bsw);

    // fvec = rna(sampled + pos_emb)
    pe_gemm<<<QN * 8 / 128, 256>>>(qpos, pew1, peb1, pew2, peb2, fv);

    const int MB = (QN + 255) / 256; // 157
    const size_t dsmem = STG * 2 * 4;
    mma_gemm2<1, 1><<<dim3(4, MB), 256, dsmem>>>(fv, w1, cb1, h1, QN, 1024, 512);
    mma_gemm2<1, 1><<<dim3(4, MB), 256, dsmem>>>(h1, w2, cb2, h2, QN, 512, 512);
    mma_gemm2<1, 1><<<dim3(4, MB), 256, dsmem>>>(h2, w3, cb3, h1, QN, 512, 512);
    mma_gemm2<0, 0><<<dim3(1, MB), 256, dsmem>>>(h1, w4, cb4, h2, QN, 512, 128);

    transpose_out_kernel<<<dim3(QN / 32, 4), tb>>>(h2, out);
}

// round 5
// speedup vs baseline: 1.0765x; 1.0765x over previous
#include <cuda_runtime.h>
#include <cuda_bf16.h>
#include <math.h>
#include <stdint.h>

// ---------------- problem constants ----------------
#define QN      40000
#define NCAM    6
#define IMGW    480.0f
#define IMGH    224.0f

// level geometry
#define HW0 6720
#define HW1 1680
#define HW2 420
#define HW3 105
#define TOTPIX 8925

// scratch buffers
__device__ float g_tf[(size_t)TOTPIX * NCAM * 128];          // 27.4 MB transposed features
__device__ float g_fvec[(size_t)QN * 1024];                   // 163.8 MB
__device__ float g_h1[(size_t)QN * 512];                      // 81.9 MB
__device__ float g_h2[(size_t)QN * 512];                      // 81.9 MB
__device__ float g_w1[1024 * 512];                            // tf32-rounded weights
__device__ float g_w2[512 * 512];
__device__ float g_w3[512 * 512];
__device__ float g_w4[512 * 128];

__device__ __forceinline__ uint32_t f2tf(float x) {
    uint32_t u;
    asm("cvt.rna.tf32.f32 %0, %1;" : "=r"(u) : "f"(x));
    return u;
}
__device__ __forceinline__ float rnatf(float x) {
    return __uint_as_float(f2tf(x));
}
__device__ __forceinline__ void cp16(uint32_t dst, const void* src, bool ok) {
    int sz = ok ? 16 : 0;
    asm volatile("cp.async.cg.shared.global [%0], [%1], 16, %2;"
                 :: "r"(dst), "l"(src), "r"(sz));
}

// ---------------- tf32 round weights ----------------
__global__ void round_tf32_kernel(const float* __restrict__ in, float* __restrict__ out, int n) {
    int i = blockIdx.x * 256 + threadIdx.x;
    if (i < n) out[i] = rnatf(in[i]);
}

// ---------------- feat transpose: [n][128ch][HW] -> [n][HW][128] ----------------
__global__ void transpose_feat_kernel(const float* __restrict__ feat,
                                      float* __restrict__ dst, int HW) {
    __shared__ float s[32][33];
    int n    = blockIdx.z;
    int ch0  = blockIdx.y * 32;
    int pix0 = blockIdx.x * 32;
    int tx = threadIdx.x, ty = threadIdx.y;

    int pix = pix0 + tx;
    int ch  = ch0 + ty;
    if (pix < HW)
        s[ty][tx] = feat[((size_t)(n * 128 + ch)) * HW + pix];
    __syncthreads();
    int pixw = pix0 + ty;
    int chw  = ch0 + tx;
    if (pixw < HW)
        dst[((size_t)n * HW + pixw) * 128 + chw] = s[tx][ty];
}

// ---------------- sampling + scale softmax + projection ----------------
__global__ __launch_bounds__(128) void sample_kernel(
    const float* __restrict__ query,   // [Q][P][128]
    const float* __restrict__ qpos,    // [Z=8][Q][3]
    const float* __restrict__ l2i,     // [6][4][4]
    const float* __restrict__ Wsw,     // [128][16]
    const float* __restrict__ bsw)     // [16]
{
    __shared__ __align__(16) float s_q[1024];
    __shared__ __align__(16) float s_wsw[2048];
    __shared__ float s_logit[128];
    __shared__ float s_sw[128];
    __shared__ float s_bsw[16];
    __shared__ float s_l2i[96];
    __shared__ float s_qp[8][3];
    __shared__ float s_u[8], s_v[8];
    __shared__ int   s_cam[8], s_ok[8];

    const int q   = blockIdx.x;
    const int tid = threadIdx.x;

    {
        const float4* qv = (const float4*)(query + (size_t)q * 1024);
        float4* d = (float4*)s_q;
        d[tid] = qv[tid]; d[tid + 128] = qv[tid + 128];

        const float4* wv = (const float4*)Wsw;
        float4* sw4 = (float4*)s_wsw;
        sw4[tid] = wv[tid]; sw4[tid + 128] = wv[tid + 128];
        sw4[tid + 256] = wv[tid + 256]; sw4[tid + 384] = wv[tid + 384];

        if (tid < 16) s_bsw[tid] = bsw[tid];
        if (tid < 96) s_l2i[tid] = l2i[tid];
        if (tid < 24) s_qp[tid / 3][tid % 3] = qpos[((size_t)(tid / 3) * QN + q) * 3 + (tid % 3)];
    }
    __syncthreads();

    // scale-weight logits
    {
        int p = tid >> 4, gl = tid & 15;
        float acc = s_bsw[gl];
        const float* qrow = s_q + p * 128;
        #pragma unroll 8
        for (int k = 0; k < 128; k++) acc += qrow[k] * s_wsw[k * 16 + gl];
        s_logit[tid] = acc;
    }
    // projection: first valid camera per point
    if (tid < 8) {
        int p = tid;
        float X = s_qp[p][0] * 100.f - 50.f;
        float Y = s_qp[p][1] * 100.f - 50.f;
        float Zc = s_qp[p][2] * 8.f - 4.f;
        int found = 0, cam = 0; float uu = 0.f, vv = 0.f;
        #pragma unroll
        for (int n = 0; n < 6; n++) {
            const float* M = s_l2i + n * 16;
            float c0 = M[0] * X + M[1] * Y + M[2]  * Zc + M[3];
            float c1 = M[4] * X + M[5] * Y + M[6]  * Zc + M[7];
            float c2 = M[8] * X + M[9] * Y + M[10] * Zc + M[11];
            float den = fmaxf(c2, 1e-6f);
            float u = (c0 / den) / IMGW;
            float v = (c1 / den) / IMGH;
            bool val = (c2 > 1e-6f) && (u > 0.f) && (u < 1.f) && (v > 0.f) && (v < 1.f);
            if (val && !found) { found = 1; cam = n; uu = u; vv = v; }
        }
        s_cam[p] = cam; s_ok[p] = found; s_u[p] = uu; s_v[p] = vv;
    }
    __syncthreads();

    // softmax over levels per (p,g)
    if (tid < 32) {
        int base = tid * 4;
        float a = s_logit[base], b = s_logit[base + 1], c = s_logit[base + 2], d = s_logit[base + 3];
        float m = fmaxf(fmaxf(a, b), fmaxf(c, d));
        float ea = expf(a - m), eb = expf(b - m), ec = expf(c - m), ed = expf(d - m);
        float inv = 1.f / (ea + eb + ec + ed);
        s_sw[base] = ea * inv; s_sw[base + 1] = eb * inv;
        s_sw[base + 2] = ec * inv; s_sw[base + 3] = ed * inv;
    }
    __syncthreads();

    const int cch = tid;
    const int LW[4]    = {120, 60, 30, 15};
    const int LH[4]    = {56, 28, 14, 7};
    const int LHW[4]   = {HW0, HW1, HW2, HW3};
    const int LBASE[4] = {0, HW0 * NCAM * 128, (HW0 + HW1) * NCAM * 128, (HW0 + HW1 + HW2) * NCAM * 128};

    const int g = cch >> 5;
    float* outp = g_fvec + (size_t)q * 1024 + cch;

    #pragma unroll 1
    for (int p = 0; p < 8; p++) {
        float sval = 0.f;
        if (s_ok[p]) {
            int cam = s_cam[p];
            float u = s_u[p], v = s_v[p];
            const float* swp = s_sw + p * 16 + g * 4;
            #pragma unroll
            for (int l = 0; l < 4; l++) {
                int w = LW[l], h = LH[l];
                const float* base = g_tf + LBASE[l] + (size_t)cam * LHW[l] * 128;
                float x = u * (float)w - 0.5f;
                float y = v * (float)h - 0.5f;
                float xf = floorf(x), yf = floorf(y);
                float wx = x - xf, wy = y - yf;
                int x0 = (int)xf, y0 = (int)yf;
                int x1 = x0 + 1, y1 = y0 + 1;
                bool ix0 = (x0 >= 0) && (x0 < w);
                bool ix1 = (x1 < w);
                bool iy0 = (y0 >= 0) && (y0 < h);
                bool iy1 = (y1 < h);
                float v00 = (iy0 && ix0) ? base[((size_t)y0 * w + x0) * 128 + cch] : 0.f;
                float v01 = (iy0 && ix1) ? base[((size_t)y0 * w + x1) * 128 + cch] : 0.f;
                float v10 = (iy1 && ix0) ? base[((size_t)y1 * w + x0) * 128 + cch] : 0.f;
                float v11 = (iy1 && ix1) ? base[((size_t)y1 * w + x1) * 128 + cch] : 0.f;
                float bil = v00 * (1.f - wx) * (1.f - wy) + v01 * wx * (1.f - wy)
                          + v10 * (1.f - wx) * wy + v11 * wx * wy;
                sval += bil * swp[l];
            }
        }
        outp[p * 128] = sval;
    }
}

// ---------------- tf32 GEMM v3: 128x128 block, cp.async 2-stage, occ 2 ----------------
// A and W must already be tf32-rounded (rna). grid = (N/128, ceil(M/128)).
#define ASZ (128 * 36)
#define BSZ (32 * 136)
#define STG (ASZ + BSZ)

template <int RELU, int ROUND>
__global__ __launch_bounds__(256, 2) void mma_gemm3(
    const float* __restrict__ A, const float* __restrict__ W,
    const float* __restrict__ bias, float* __restrict__ C,
    int M, int K, int N)
{
    extern __shared__ uint32_t sm[];

    const int tid  = threadIdx.x;
    const int lane = tid & 31;
    const int warp = tid >> 5;
    const int wm = warp >> 2;          // 0..1 (64 rows each)
    const int wn = warp & 3;           // 0..3 (32 cols each)
    const int bn = blockIdx.x * 128, bm = blockIdx.y * 128;

    float c[4][4][4];
    #pragma unroll
    for (int i = 0; i < 4; i++)
        #pragma unroll
        for (int j = 0; j < 4; j++) {
            c[i][j][0] = 0.f; c[i][j][1] = 0.f; c[i][j][2] = 0.f; c[i][j][3] = 0.f;
        }

    const int arow = tid >> 3, akq = tid & 7;    // A: 32 rows per i, 4 iters
    const int bkr  = tid >> 5, bnq = tid & 31;   // B: 8 k-rows per i, 4 iters

    uint32_t as_base[2], bs_base[2];
    #pragma unroll
    for (int s = 0; s < 2; s++) {
        as_base[s] = (uint32_t)__cvta_generic_to_shared(sm + s * STG);
        bs_base[s] = (uint32_t)__cvta_generic_to_shared(sm + s * STG + ASZ);
    }

    auto load_slab = [&](int k0, int s) {
        #pragma unroll
        for (int i = 0; i < 4; i++) {
            int row = arow + 32 * i;
            bool ok = (bm + row) < M;
            const float* src = A + (size_t)(bm + (ok ? row : 0)) * K + k0 + akq * 4;
            cp16(as_base[s] + (row * 36 + akq * 4) * 4, src, ok);
        }
        #pragma unroll
        for (int i = 0; i < 4; i++) {
            int kr = bkr + 8 * i;
            const float* src = W + (size_t)(k0 + kr) * N + bn + bnq * 4;
            cp16(bs_base[s] + (kr * 136 + bnq * 4) * 4, src, true);
        }
    };

    load_slab(0, 0);
    asm volatile("cp.async.commit_group;");

    for (int k0 = 0, s = 0; k0 < K; k0 += 32, s ^= 1) {
        if (k0 + 32 < K) load_slab(k0 + 32, s ^ 1);
        asm volatile("cp.async.commit_group;");
        asm volatile("cp.async.wait_group 1;");
        __syncthreads();

        const uint32_t* As = sm + s * STG;
        const uint32_t* Bs = sm + s * STG + ASZ;

        #pragma unroll
        for (int kt = 0; kt < 4; kt++) {
            const int kk = kt * 8 + (lane & 3);
            uint32_t a[4][4], b[4][2];
            const int mrow = wm * 64 + (lane >> 2);
            #pragma unroll
            for (int mt = 0; mt < 4; mt++) {
                int m = mrow + mt * 16;
                a[mt][0] = As[m * 36 + kk];
                a[mt][1] = As[(m + 8) * 36 + kk];
                a[mt][2] = As[m * 36 + kk + 4];
                a[mt][3] = As[(m + 8) * 36 + kk + 4];
            }
            const int ncol = wn * 32 + (lane >> 2);
            #pragma unroll
            for (int nt = 0; nt < 4; nt++) {
                int n = ncol + nt * 8;
                b[nt][0] = Bs[kk * 136 + n];
                b[nt][1] = Bs[(kk + 4) * 136 + n];
            }
            #pragma unroll
            for (int mt = 0; mt < 4; mt++)
                #pragma unroll
                for (int nt = 0; nt < 4; nt++) {
                    asm volatile(
                        "mma.sync.aligned.m16n8k8.row.col.f32.tf32.tf32.f32 "
                        "{%0,%1,%2,%3}, {%4,%5,%6,%7}, {%8,%9}, {%0,%1,%2,%3};"
                        : "+f"(c[mt][nt][0]), "+f"(c[mt][nt][1]),
                          "+f"(c[mt][nt][2]), "+f"(c[mt][nt][3])
                        : "r"(a[mt][0]), "r"(a[mt][1]), "r"(a[mt][2]), "r"(a[mt][3]),
                          "r"(b[nt][0]), "r"(b[nt][1]));
                }
        }
        __syncthreads();
    }

    #pragma unroll
    for (int mt = 0; mt < 4; mt++) {
        int row0 = bm + wm * 64 + mt * 16 + (lane >> 2);
        #pragma unroll
        for (int nt = 0; nt < 4; nt++) {
            int col = bn + wn * 32 + nt * 8 + (lane & 3) * 2;
            float b0 = bias[col], b1 = bias[col + 1];
            #pragma unroll
            for (int half = 0; half < 2; half++) {
                int row = row0 + half * 8;
                if (row < M) {
                    float v0 = c[mt][nt][half * 2 + 0] + b0;
                    float v1 = c[mt][nt][half * 2 + 1] + b1;
                    if (RELU)  { v0 = fmaxf(v0, 0.f); v1 = fmaxf(v1, 0.f); }
                    if (ROUND) { v0 = rnatf(v0); v1 = rnatf(v1); }
                    float* cp = C + (size_t)row * N + col;
                    cp[0] = v0; cp[1] = v1;
                }
            }
        }
    }
}

// ---------------- fused positional-encoding GEMM ----------------
// fvec[r,col] = rna(fvec[r,col] + relu(qp[r]@pe_w1+pe_b1) @ pe_w2 + pe_b2)
__global__ __launch_bounds__(256, 2) void pe_gemm(
    const float* __restrict__ qpos,    // [8][Q][3]
    const float* __restrict__ pew1,    // [3][256]
    const float* __restrict__ peb1,    // [256]
    const float* __restrict__ pew2,    // [256][128]
    const float* __restrict__ peb2,    // [128]
    float* __restrict__ C)             // fvec
{
    __shared__ uint32_t As[128 * 36];
    __shared__ uint32_t Bs[32 * 136];
    __shared__ float sw1[768];
    __shared__ float sb1[256];
    __shared__ float sxyz[128 * 3];

    const int tid  = threadIdx.x;
    const int lane = tid & 31;
    const int warp = tid >> 5;
    const int wm = warp >> 2;
    const int wn = warp & 3;
    const int bm = blockIdx.x * 128;

    sw1[tid] = pew1[tid]; sw1[tid + 256] = pew1[tid + 256]; sw1[tid + 512] = pew1[tid + 512];
    if (tid < 256) sb1[tid] = peb1[tid];
    if (tid < 128) {
        int r = bm + tid;
        int q = r >> 3, p = r & 7;
        const float* xp = qpos + ((size_t)p * QN + q) * 3;
        sxyz[tid * 3 + 0] = xp[0];
        sxyz[tid * 3 + 1] = xp[1];
        sxyz[tid * 3 + 2] = xp[2];
    }

    float c[4][4][4];
    #pragma unroll
    for (int i = 0; i < 4; i++)
        #pragma unroll
        for (int j = 0; j < 4; j++) {
            c[i][j][0] = 0.f; c[i][j][1] = 0.f; c[i][j][2] = 0.f; c[i][j][3] = 0.f;
        }

    const int am = tid >> 3, akq = tid & 7;
    const int bkr = tid >> 5, bnq = tid & 31;

    __syncthreads();

    for (int k0 = 0; k0 < 256; k0 += 32) {
        __syncthreads();
        #pragma unroll
        for (int i = 0; i < 4; i++) {
            int m = am + 32 * i;
            float x0 = sxyz[m * 3], x1 = sxyz[m * 3 + 1], x2 = sxyz[m * 3 + 2];
            uint32_t* p = &As[m * 36 + akq * 4];
            #pragma unroll
            for (int t = 0; t < 4; t++) {
                int j = k0 + akq * 4 + t;
                float h = sb1[j] + x0 * sw1[j] + x1 * sw1[256 + j] + x2 * sw1[512 + j];
                p[t] = f2tf(fmaxf(h, 0.f));
            }
        }
        #pragma unroll
        for (int i = 0; i < 4; i++) {
            float4 b4 = *(const float4*)(pew2 + (size_t)(k0 + bkr + 8 * i) * 128 + bnq * 4);
            uint32_t* p = &Bs[(bkr + 8 * i) * 136 + bnq * 4];
            p[0] = f2tf(b4.x); p[1] = f2tf(b4.y); p[2] = f2tf(b4.z); p[3] = f2tf(b4.w);
        }
        __syncthreads();

        #pragma unroll
        for (int kt = 0; kt < 4; kt++) {
            const int kk = kt * 8 + (lane & 3);
            uint32_t a[4][4], b[4][2];
            const int mrow = wm * 64 + (lane >> 2);
            #pragma unroll
            for (int mt = 0; mt < 4; mt++) {
                int m = mrow + mt * 16;
                a[mt][0] = As[m * 36 + kk];
                a[mt][1] = As[(m + 8) * 36 + kk];
                a[mt][2] = As[m * 36 + kk + 4];
                a[mt][3] = As[(m + 8) * 36 + kk + 4];
            }
            const int ncol = wn * 32 + (lane >> 2);
            #pragma unroll
            for (int nt = 0; nt < 4; nt++) {
                int n = ncol + nt * 8;
                b[nt][0] = Bs[kk * 136 + n];
                b[nt][1] = Bs[(kk + 4) * 136 + n];
            }
            #pragma unroll
            for (int mt = 0; mt < 4; mt++)
                #pragma unroll
                for (int nt = 0; nt < 4; nt++) {
                    asm volatile(
                        "mma.sync.aligned.m16n8k8.row.col.f32.tf32.tf32.f32 "
                        "{%0,%1,%2,%3}, {%4,%5,%6,%7}, {%8,%9}, {%0,%1,%2,%3};"
                        : "+f"(c[mt][nt][0]), "+f"(c[mt][nt][1]),
                          "+f"(c[mt][nt][2]), "+f"(c[mt][nt][3])
                        : "r"(a[mt][0]), "r"(a[mt][1]), "r"(a[mt][2]), "r"(a[mt][3]),
                          "r"(b[nt][0]), "r"(b[nt][1]));
                }
        }
    }

    #pragma unroll
    for (int mt = 0; mt < 4; mt++) {
        int row0 = bm + wm * 64 + mt * 16 + (lane >> 2);
        #pragma unroll
        for (int nt = 0; nt < 4; nt++) {
            int col = wn * 32 + nt * 8 + (lane & 3) * 2;
            float b0 = peb2[col], b1 = peb2[col + 1];
            #pragma unroll
            for (int half = 0; half < 2; half++) {
                int row = row0 + half * 8;
                float* cp = C + (size_t)row * 128 + col;
                cp[0] = rnatf(cp[0] + c[mt][nt][half * 2 + 0] + b0);
                cp[1] = rnatf(cp[1] + c[mt][nt][half * 2 + 1] + b1);
            }
        }
    }
}

// ---------------- final transpose: [Q][128] -> [128][Q] ----------------
__global__ void transpose_out_kernel(const float* __restrict__ in, float* __restrict__ out) {
    __shared__ float s[32][33];
    int q0 = blockIdx.x * 32, e0 = blockIdx.y * 32;
    int tx = threadIdx.x, ty = threadIdx.y;
    s[ty][tx] = in[(size_t)(q0 + ty) * 128 + (e0 + tx)];
    __syncthreads();
    out[(size_t)(e0 + ty) * QN + (q0 + tx)] = s[tx][ty];
}

// ---------------- launch ----------------
extern "C" void kernel_launch(void* const* d_in, const int* in_sizes, int n_in,
                              void* d_out, int out_size) {
    const float* feat0 = (const float*)d_in[0];
    const float* feat1 = (const float*)d_in[1];
    const float* feat2 = (const float*)d_in[2];
    const float* feat3 = (const float*)d_in[3];
    const float* query = (const float*)d_in[4];
    const float* qpos  = (const float*)d_in[5];
    const float* l2i   = (const float*)d_in[6];
    const float* Wsw   = (const float*)d_in[7];
    const float* bsw   = (const float*)d_in[8];
    const float* pew1  = (const float*)d_in[9];
    const float* peb1  = (const float*)d_in[10];
    const float* pew2  = (const float*)d_in[11];
    const float* peb2  = (const float*)d_in[12];
    const float* cw1   = (const float*)d_in[13];
    const float* cb1   = (const float*)d_in[14];
    const float* cw2   = (const float*)d_in[15];
    const float* cb2   = (const float*)d_in[16];
    const float* cw3   = (const float*)d_in[17];
    const float* cb3   = (const float*)d_in[18];
    const float* cw4   = (const float*)d_in[19];
    const float* cb4   = (const float*)d_in[20];
    float* out = (float*)d_out;

    float* tf;  cudaGetSymbolAddress((void**)&tf,  g_tf);
    float* fv;  cudaGetSymbolAddress((void**)&fv,  g_fvec);
    float* h1;  cudaGetSymbolAddress((void**)&h1,  g_h1);
    float* h2;  cudaGetSymbolAddress((void**)&h2,  g_h2);
    float* w1;  cudaGetSymbolAddress((void**)&w1,  g_w1);
    float* w2;  cudaGetSymbolAddress((void**)&w2,  g_w2);
    float* w3;  cudaGetSymbolAddress((void**)&w3,  g_w3);
    float* w4;  cudaGetSymbolAddress((void**)&w4,  g_w4);

    const size_t dsmem = STG * 2 * 4;   // 71.7 KB
    cudaFuncSetAttribute(mma_gemm3<1, 1>, cudaFuncAttributeMaxDynamicSharedMemorySize, (int)dsmem);
    cudaFuncSetAttribute(mma_gemm3<0, 0>, cudaFuncAttributeMaxDynamicSharedMemorySize, (int)dsmem);

    dim3 tb(32, 32);
    transpose_feat_kernel<<<dim3((HW0 + 31) / 32, 4, 6), tb>>>(feat0, tf, HW0);
    transpose_feat_kernel<<<dim3((HW1 + 31) / 32, 4, 6), tb>>>(feat1, tf + (size_t)HW0 * NCAM * 128, HW1);
    transpose_feat_kernel<<<dim3((HW2 + 31) / 32, 4, 6), tb>>>(feat2, tf + (size_t)(HW0 + HW1) * NCAM * 128, HW2);
    transpose_feat_kernel<<<dim3((HW3 + 31) / 32, 4, 6), tb>>>(feat3, tf + (size_t)(HW0 + HW1 + HW2) * NCAM * 128, HW3);

    round_tf32_kernel<<<(1024 * 512 + 255) / 256, 256>>>(cw1, w1, 1024 * 512);
    round_tf32_kernel<<<(512 * 512 + 255) / 256, 256>>>(cw2, w2, 512 * 512);
    round_tf32_kernel<<<(512 * 512 + 255) / 256, 256>>>(cw3, w3, 512 * 512);
    round_tf32_kernel<<<(512 * 128 + 255) / 256, 256>>>(cw4, w4, 512 * 128);

    sample_kernel<<<QN, 128>>>(query, qpos, l2i, Wsw, bsw);

    // fvec = rna(sampled + pos_emb)
    pe_gemm<<<QN * 8 / 128, 256>>>(qpos, pew1, peb1, pew2, peb2, fv);

    const int MB = (QN + 127) / 128; // 313
    mma_gemm3<1, 1><<<dim3(4, MB), 256, dsmem>>>(fv, w1, cb1, h1, QN, 1024, 512);
    mma_gemm3<1, 1><<<dim3(4, MB), 256, dsmem>>>(h1, w2, cb2, h2, QN, 512, 512);
    mma_gemm3<1, 1><<<dim3(4, MB), 256, dsmem>>>(h2, w3, cb3, h1, QN, 512, 512);
    mma_gemm3<0, 0><<<dim3(1, MB), 256, dsmem>>>(h1, w4, cb4, h2, QN, 512, 128);

    transpose_out_kernel<<<dim3(QN / 32, 4), tb>>>(h2, out);
}

// round 6
// speedup vs baseline: 1.0989x; 1.0209x over previous
#include <cuda_runtime.h>
#include <cuda_bf16.h>
#include <math.h>
#include <stdint.h>

// ---------------- problem constants ----------------
#define QN      40000
#define NCAM    6
#define IMGW    480.0f
#define IMGH    224.0f

// level geometry
#define HW0 6720
#define HW1 1680
#define HW2 420
#define HW3 105
#define TOTPIX 8925

// scratch buffers
__device__ float g_tf[(size_t)TOTPIX * NCAM * 128];          // 27.4 MB transposed features
__device__ float g_fvec[(size_t)QN * 1024];                   // 163.8 MB
__device__ float g_h1[(size_t)QN * 512];                      // 81.9 MB
__device__ float g_h2[(size_t)QN * 512];                      // 81.9 MB
__device__ float g_w1[1024 * 512];                            // tf32-rounded weights
__device__ float g_w2[512 * 512];
__device__ float g_w3[512 * 512];
__device__ float g_w4[512 * 128];

__device__ __forceinline__ uint32_t f2tf(float x) {
    uint32_t u;
    asm("cvt.rna.tf32.f32 %0, %1;" : "=r"(u) : "f"(x));
    return u;
}
__device__ __forceinline__ float rnatf(float x) {
    return __uint_as_float(f2tf(x));
}
__device__ __forceinline__ void cp16(uint32_t dst, const void* src, bool ok) {
    int sz = ok ? 16 : 0;
    asm volatile("cp.async.cg.shared.global [%0], [%1], 16, %2;"
                 :: "r"(dst), "l"(src), "r"(sz));
}

// ---------------- tf32 round weights ----------------
__global__ void round_tf32_kernel(const float* __restrict__ in, float* __restrict__ out, int n) {
    int i = blockIdx.x * 256 + threadIdx.x;
    if (i < n) out[i] = rnatf(in[i]);
}

// ---------------- feat transpose: [n][128ch][HW] -> [n][HW][128] ----------------
__global__ void transpose_feat_kernel(const float* __restrict__ feat,
                                      float* __restrict__ dst, int HW) {
    __shared__ float s[32][33];
    int n    = blockIdx.z;
    int ch0  = blockIdx.y * 32;
    int pix0 = blockIdx.x * 32;
    int tx = threadIdx.x, ty = threadIdx.y;

    int pix = pix0 + tx;
    int ch  = ch0 + ty;
    if (pix < HW)
        s[ty][tx] = feat[((size_t)(n * 128 + ch)) * HW + pix];
    __syncthreads();
    int pixw = pix0 + ty;
    int chw  = ch0 + tx;
    if (pixw < HW)
        dst[((size_t)n * HW + pixw) * 128 + chw] = s[tx][ty];
}

// ---------------- sampling + scale softmax + projection ----------------
__global__ __launch_bounds__(128) void sample_kernel(
    const float* __restrict__ query,   // [Q][P][128]
    const float* __restrict__ qpos,    // [Z=8][Q][3]
    const float* __restrict__ l2i,     // [6][4][4]
    const float* __restrict__ Wsw,     // [128][16]
    const float* __restrict__ bsw)     // [16]
{
    __shared__ __align__(16) float s_q[1024];
    __shared__ __align__(16) float s_wsw[2048];
    __shared__ float s_logit[128];
    __shared__ float s_sw[128];
    __shared__ float s_bsw[16];
    __shared__ float s_l2i[96];
    __shared__ float s_qp[8][3];
    __shared__ float s_u[8], s_v[8];
    __shared__ int   s_cam[8], s_ok[8];

    const int q   = blockIdx.x;
    const int tid = threadIdx.x;

    {
        const float4* qv = (const float4*)(query + (size_t)q * 1024);
        float4* d = (float4*)s_q;
        d[tid] = qv[tid]; d[tid + 128] = qv[tid + 128];

        const float4* wv = (const float4*)Wsw;
        float4* sw4 = (float4*)s_wsw;
        sw4[tid] = wv[tid]; sw4[tid + 128] = wv[tid + 128];
        sw4[tid + 256] = wv[tid + 256]; sw4[tid + 384] = wv[tid + 384];

        if (tid < 16) s_bsw[tid] = bsw[tid];
        if (tid < 96) s_l2i[tid] = l2i[tid];
        if (tid < 24) s_qp[tid / 3][tid % 3] = qpos[((size_t)(tid / 3) * QN + q) * 3 + (tid % 3)];
    }
    __syncthreads();

    // scale-weight logits
    {
        int p = tid >> 4, gl = tid & 15;
        float acc = s_bsw[gl];
        const float* qrow = s_q + p * 128;
        #pragma unroll 8
        for (int k = 0; k < 128; k++) acc += qrow[k] * s_wsw[k * 16 + gl];
        s_logit[tid] = acc;
    }
    // projection: first valid camera per point
    if (tid < 8) {
        int p = tid;
        float X = s_qp[p][0] * 100.f - 50.f;
        float Y = s_qp[p][1] * 100.f - 50.f;
        float Zc = s_qp[p][2] * 8.f - 4.f;
        int found = 0, cam = 0; float uu = 0.f, vv = 0.f;
        #pragma unroll
        for (int n = 0; n < 6; n++) {
            const float* M = s_l2i + n * 16;
            float c0 = M[0] * X + M[1] * Y + M[2]  * Zc + M[3];
            float c1 = M[4] * X + M[5] * Y + M[6]  * Zc + M[7];
            float c2 = M[8] * X + M[9] * Y + M[10] * Zc + M[11];
            float den = fmaxf(c2, 1e-6f);
            float u = (c0 / den) / IMGW;
            float v = (c1 / den) / IMGH;
            bool val = (c2 > 1e-6f) && (u > 0.f) && (u < 1.f) && (v > 0.f) && (v < 1.f);
            if (val && !found) { found = 1; cam = n; uu = u; vv = v; }
        }
        s_cam[p] = cam; s_ok[p] = found; s_u[p] = uu; s_v[p] = vv;
    }
    __syncthreads();

    // softmax over levels per (p,g)
    if (tid < 32) {
        int base = tid * 4;
        float a = s_logit[base], b = s_logit[base + 1], c = s_logit[base + 2], d = s_logit[base + 3];
        float m = fmaxf(fmaxf(a, b), fmaxf(c, d));
        float ea = expf(a - m), eb = expf(b - m), ec = expf(c - m), ed = expf(d - m);
        float inv = 1.f / (ea + eb + ec + ed);
        s_sw[base] = ea * inv; s_sw[base + 1] = eb * inv;
        s_sw[base + 2] = ec * inv; s_sw[base + 3] = ed * inv;
    }
    __syncthreads();

    const int cch = tid;
    const int LW[4]    = {120, 60, 30, 15};
    const int LH[4]    = {56, 28, 14, 7};
    const int LHW[4]   = {HW0, HW1, HW2, HW3};
    const int LBASE[4] = {0, HW0 * NCAM * 128, (HW0 + HW1) * NCAM * 128, (HW0 + HW1 + HW2) * NCAM * 128};

    const int g = cch >> 5;
    float* outp = g_fvec + (size_t)q * 1024 + cch;

    #pragma unroll 1
    for (int p = 0; p < 8; p++) {
        float sval = 0.f;
        if (s_ok[p]) {
            int cam = s_cam[p];
            float u = s_u[p], v = s_v[p];
            const float* swp = s_sw + p * 16 + g * 4;
            #pragma unroll
            for (int l = 0; l < 4; l++) {
                int w = LW[l], h = LH[l];
                const float* base = g_tf + LBASE[l] + (size_t)cam * LHW[l] * 128;
                float x = u * (float)w - 0.5f;
                float y = v * (float)h - 0.5f;
                float xf = floorf(x), yf = floorf(y);
                float wx = x - xf, wy = y - yf;
                int x0 = (int)xf, y0 = (int)yf;
                int x1 = x0 + 1, y1 = y0 + 1;
                bool ix0 = (x0 >= 0) && (x0 < w);
                bool ix1 = (x1 < w);
                bool iy0 = (y0 >= 0) && (y0 < h);
                bool iy1 = (y1 < h);
                float v00 = (iy0 && ix0) ? base[((size_t)y0 * w + x0) * 128 + cch] : 0.f;
                float v01 = (iy0 && ix1) ? base[((size_t)y0 * w + x1) * 128 + cch] : 0.f;
                float v10 = (iy1 && ix0) ? base[((size_t)y1 * w + x0) * 128 + cch] : 0.f;
                float v11 = (iy1 && ix1) ? base[((size_t)y1 * w + x1) * 128 + cch] : 0.f;
                float bil = v00 * (1.f - wx) * (1.f - wy) + v01 * wx * (1.f - wy)
                          + v10 * (1.f - wx) * wy + v11 * wx * wy;
                sval += bil * swp[l];
            }
        }
        outp[p * 128] = sval;
    }
}

// ---------------- tf32 GEMM v4: 128x128 block, 128 thr, 64x64 warp tiles, occ 2 ----------------
// A and W must already be tf32-rounded (rna). grid = (N/128, ceil(M/128)).
#define ASZ (128 * 36)
#define BSZ (32 * 136)
#define STG (ASZ + BSZ)

template <int RELU, int ROUND>
__global__ __launch_bounds__(128, 2) void mma_gemm4(
    const float* __restrict__ A, const float* __restrict__ W,
    const float* __restrict__ bias, float* __restrict__ C,
    int M, int K, int N)
{
    extern __shared__ uint32_t sm[];

    const int tid  = threadIdx.x;
    const int lane = tid & 31;
    const int warp = tid >> 5;        // 0..3
    const int wm = warp >> 1;         // 0..1 (64 rows)
    const int wn = warp & 1;          // 0..1 (64 cols)
    const int bn = blockIdx.x * 128, bm = blockIdx.y * 128;

    float c[4][8][4];
    #pragma unroll
    for (int i = 0; i < 4; i++)
        #pragma unroll
        for (int j = 0; j < 8; j++) {
            c[i][j][0] = 0.f; c[i][j][1] = 0.f; c[i][j][2] = 0.f; c[i][j][3] = 0.f;
        }

    uint32_t as_base[2], bs_base[2];
    #pragma unroll
    for (int s = 0; s < 2; s++) {
        as_base[s] = (uint32_t)__cvta_generic_to_shared(sm + s * STG);
        bs_base[s] = (uint32_t)__cvta_generic_to_shared(sm + s * STG + ASZ);
    }

    // loaders: 128 threads, 8 float4 each for A (128x32) and B (32x128)
    auto load_slab = [&](int k0, int s) {
        #pragma unroll
        for (int i = 0; i < 8; i++) {
            int idx = tid + 128 * i;
            int row = idx >> 3, kq = idx & 7;
            bool ok = (bm + row) < M;
            const float* src = A + (size_t)(bm + (ok ? row : 0)) * K + k0 + kq * 4;
            cp16(as_base[s] + (row * 36 + kq * 4) * 4, src, ok);
        }
        #pragma unroll
        for (int i = 0; i < 8; i++) {
            int idx = tid + 128 * i;
            int kr = idx >> 5, nq = idx & 31;
            const float* src = W + (size_t)(k0 + kr) * N + bn + nq * 4;
            cp16(bs_base[s] + (kr * 136 + nq * 4) * 4, src, true);
        }
    };

    load_slab(0, 0);
    asm volatile("cp.async.commit_group;");

    for (int k0 = 0, s = 0; k0 < K; k0 += 32, s ^= 1) {
        if (k0 + 32 < K) load_slab(k0 + 32, s ^ 1);
        asm volatile("cp.async.commit_group;");
        asm volatile("cp.async.wait_group 1;");
        __syncthreads();

        const uint32_t* As = sm + s * STG;
        const uint32_t* Bs = sm + s * STG + ASZ;

        #pragma unroll
        for (int kt = 0; kt < 4; kt++) {
            const int kk = kt * 8 + (lane & 3);
            uint32_t a[4][4], b[8][2];
            const int mrow = wm * 64 + (lane >> 2);
            #pragma unroll
            for (int mt = 0; mt < 4; mt++) {
                int m = mrow + mt * 16;
                a[mt][0] = As[m * 36 + kk];
                a[mt][1] = As[(m + 8) * 36 + kk];
                a[mt][2] = As[m * 36 + kk + 4];
                a[mt][3] = As[(m + 8) * 36 + kk + 4];
            }
            const int nc = wn * 64 + (lane >> 2);
            #pragma unroll
            for (int nt = 0; nt < 8; nt++) {
                int n = nc + nt * 8;
                b[nt][0] = Bs[kk * 136 + n];
                b[nt][1] = Bs[(kk + 4) * 136 + n];
            }
            #pragma unroll
            for (int mt = 0; mt < 4; mt++)
                #pragma unroll
                for (int nt = 0; nt < 8; nt++) {
                    asm volatile(
                        "mma.sync.aligned.m16n8k8.row.col.f32.tf32.tf32.f32 "
                        "{%0,%1,%2,%3}, {%4,%5,%6,%7}, {%8,%9}, {%0,%1,%2,%3};"
                        : "+f"(c[mt][nt][0]), "+f"(c[mt][nt][1]),
                          "+f"(c[mt][nt][2]), "+f"(c[mt][nt][3])
                        : "r"(a[mt][0]), "r"(a[mt][1]), "r"(a[mt][2]), "r"(a[mt][3]),
                          "r"(b[nt][0]), "r"(b[nt][1]));
                }
        }
        __syncthreads();
    }

    #pragma unroll
    for (int mt = 0; mt < 4; mt++) {
        int row0 = bm + wm * 64 + mt * 16 + (lane >> 2);
        #pragma unroll
        for (int nt = 0; nt < 8; nt++) {
            int col = bn + wn * 64 + nt * 8 + (lane & 3) * 2;
            float b0 = bias[col], b1 = bias[col + 1];
            #pragma unroll
            for (int half = 0; half < 2; half++) {
                int row = row0 + half * 8;
                if (row < M) {
                    float v0 = c[mt][nt][half * 2 + 0] + b0;
                    float v1 = c[mt][nt][half * 2 + 1] + b1;
                    if (RELU)  { v0 = fmaxf(v0, 0.f); v1 = fmaxf(v1, 0.f); }
                    if (ROUND) { v0 = rnatf(v0); v1 = rnatf(v1); }
                    float* cp = C + (size_t)row * N + col;
                    cp[0] = v0; cp[1] = v1;
                }
            }
        }
    }
}

// ---------------- fused positional-encoding GEMM ----------------
// fvec[r,col] = rna(fvec[r,col] + relu(qp[r]@pe_w1+pe_b1) @ pe_w2 + pe_b2)
__global__ __launch_bounds__(256, 2) void pe_gemm(
    const float* __restrict__ qpos,    // [8][Q][3]
    const float* __restrict__ pew1,    // [3][256]
    const float* __restrict__ peb1,    // [256]
    const float* __restrict__ pew2,    // [256][128]
    const float* __restrict__ peb2,    // [128]
    float* __restrict__ C)             // fvec
{
    __shared__ uint32_t As[128 * 36];
    __shared__ uint32_t Bs[32 * 136];
    __shared__ float sw1[768];
    __shared__ float sb1[256];
    __shared__ float sxyz[128 * 3];

    const int tid  = threadIdx.x;
    const int lane = tid & 31;
    const int warp = tid >> 5;
    const int wm = warp >> 2;
    const int wn = warp & 3;
    const int bm = blockIdx.x * 128;

    sw1[tid] = pew1[tid]; sw1[tid + 256] = pew1[tid + 256]; sw1[tid + 512] = pew1[tid + 512];
    if (tid < 256) sb1[tid] = peb1[tid];
    if (tid < 128) {
        int r = bm + tid;
        int q = r >> 3, p = r & 7;
        const float* xp = qpos + ((size_t)p * QN + q) * 3;
        sxyz[tid * 3 + 0] = xp[0];
        sxyz[tid * 3 + 1] = xp[1];
        sxyz[tid * 3 + 2] = xp[2];
    }

    float c[4][4][4];
    #pragma unroll
    for (int i = 0; i < 4; i++)
        #pragma unroll
        for (int j = 0; j < 4; j++) {
            c[i][j][0] = 0.f; c[i][j][1] = 0.f; c[i][j][2] = 0.f; c[i][j][3] = 0.f;
        }

    const int am = tid >> 3, akq = tid & 7;
    const int bkr = tid >> 5, bnq = tid & 31;

    __syncthreads();

    for (int k0 = 0; k0 < 256; k0 += 32) {
        __syncthreads();
        #pragma unroll
        for (int i = 0; i < 4; i++) {
            int m = am + 32 * i;
            float x0 = sxyz[m * 3], x1 = sxyz[m * 3 + 1], x2 = sxyz[m * 3 + 2];
            uint32_t* p = &As[m * 36 + akq * 4];
            #pragma unroll
            for (int t = 0; t < 4; t++) {
                int j = k0 + akq * 4 + t;
                float h = sb1[j] + x0 * sw1[j] + x1 * sw1[256 + j] + x2 * sw1[512 + j];
                p[t] = f2tf(fmaxf(h, 0.f));
            }
        }
        #pragma unroll
        for (int i = 0; i < 4; i++) {
            float4 b4 = *(const float4*)(pew2 + (size_t)(k0 + bkr + 8 * i) * 128 + bnq * 4);
            uint32_t* p = &Bs[(bkr + 8 * i) * 136 + bnq * 4];
            p[0] = f2tf(b4.x); p[1] = f2tf(b4.y); p[2] = f2tf(b4.z); p[3] = f2tf(b4.w);
        }
        __syncthreads();

        #pragma unroll
        for (int kt = 0; kt < 4; kt++) {
            const int kk = kt * 8 + (lane & 3);
            uint32_t a[4][4], b[4][2];
            const int mrow = wm * 64 + (lane >> 2);
            #pragma unroll
            for (int mt = 0; mt < 4; mt++) {
                int m = mrow + mt * 16;
                a[mt][0] = As[m * 36 + kk];
                a[mt][1] = As[(m + 8) * 36 + kk];
                a[mt][2] = As[m * 36 + kk + 4];
                a[mt][3] = As[(m + 8) * 36 + kk + 4];
            }
            const int ncol = wn * 32 + (lane >> 2);
            #pragma unroll
            for (int nt = 0; nt < 4; nt++) {
                int n = ncol + nt * 8;
                b[nt][0] = Bs[kk * 136 + n];
                b[nt][1] = Bs[(kk + 4) * 136 + n];
            }
            #pragma unroll
            for (int mt = 0; mt < 4; mt++)
                #pragma unroll
                for (int nt = 0; nt < 4; nt++) {
                    asm volatile(
                        "mma.sync.aligned.m16n8k8.row.col.f32.tf32.tf32.f32 "
                        "{%0,%1,%2,%3}, {%4,%5,%6,%7}, {%8,%9}, {%0,%1,%2,%3};"
                        : "+f"(c[mt][nt][0]), "+f"(c[mt][nt][1]),
                          "+f"(c[mt][nt][2]), "+f"(c[mt][nt][3])
                        : "r"(a[mt][0]), "r"(a[mt][1]), "r"(a[mt][2]), "r"(a[mt][3]),
                          "r"(b[nt][0]), "r"(b[nt][1]));
                }
        }
    }

    #pragma unroll
    for (int mt = 0; mt < 4; mt++) {
        int row0 = bm + wm * 64 + mt * 16 + (lane >> 2);
        #pragma unroll
        for (int nt = 0; nt < 4; nt++) {
            int col = wn * 32 + nt * 8 + (lane & 3) * 2;
            float b0 = peb2[col], b1 = peb2[col + 1];
            #pragma unroll
            for (int half = 0; half < 2; half++) {
                int row = row0 + half * 8;
                float* cp = C + (size_t)row * 128 + col;
                cp[0] = rnatf(cp[0] + c[mt][nt][half * 2 + 0] + b0);
                cp[1] = rnatf(cp[1] + c[mt][nt][half * 2 + 1] + b1);
            }
        }
    }
}

// ---------------- final transpose: [Q][128] -> [128][Q] ----------------
__global__ void transpose_out_kernel(const float* __restrict__ in, float* __restrict__ out) {
    __shared__ float s[32][33];
    int q0 = blockIdx.x * 32, e0 = blockIdx.y * 32;
    int tx = threadIdx.x, ty = threadIdx.y;
    s[ty][tx] = in[(size_t)(q0 + ty) * 128 + (e0 + tx)];
    __syncthreads();
    out[(size_t)(e0 + ty) * QN + (q0 + tx)] = s[tx][ty];
}

// ---------------- launch ----------------
extern "C" void kernel_launch(void* const* d_in, const int* in_sizes, int n_in,
                              void* d_out, int out_size) {
    const float* feat0 = (const float*)d_in[0];
    const float* feat1 = (const float*)d_in[1];
    const float* feat2 = (const float*)d_in[2];
    const float* feat3 = (const float*)d_in[3];
    const float* query = (const float*)d_in[4];
    const float* qpos  = (const float*)d_in[5];
    const float* l2i   = (const float*)d_in[6];
    const float* Wsw   = (const float*)d_in[7];
    const float* bsw   = (const float*)d_in[8];
    const float* pew1  = (const float*)d_in[9];
    const float* peb1  = (const float*)d_in[10];
    const float* pew2  = (const float*)d_in[11];
    const float* peb2  = (const float*)d_in[12];
    const float* cw1   = (const float*)d_in[13];
    const float* cb1   = (const float*)d_in[14];
    const float* cw2   = (const float*)d_in[15];
    const float* cb2   = (const float*)d_in[16];
    const float* cw3   = (const float*)d_in[17];
    const float* cb3   = (const float*)d_in[18];
    const float* cw4   = (const float*)d_in[19];
    const float* cb4   = (const float*)d_in[20];
    float* out = (float*)d_out;

    float* tf;  cudaGetSymbolAddress((void**)&tf,  g_tf);
    float* fv;  cudaGetSymbolAddress((void**)&fv,  g_fvec);
    float* h1;  cudaGetSymbolAddress((void**)&h1,  g_h1);
    float* h2;  cudaGetSymbolAddress((void**)&h2,  g_h2);
    float* w1;  cudaGetSymbolAddress((void**)&w1,  g_w1);
    float* w2;  cudaGetSymbolAddress((void**)&w2,  g_w2);
    float* w3;  cudaGetSymbolAddress((void**)&w3,  g_w3);
    float* w4;  cudaGetSymbolAddress((void**)&w4,  g_w4);

    const size_t dsmem = STG * 2 * 4;   // 71.7 KB
    cudaFuncSetAttribute(mma_gemm4<1, 1>, cudaFuncAttributeMaxDynamicSharedMemorySize, (int)dsmem);
    cudaFuncSetAttribute(mma_gemm4<0, 0>, cudaFuncAttributeMaxDynamicSharedMemorySize, (int)dsmem);

    dim3 tb(32, 32);
    transpose_feat_kernel<<<dim3((HW0 + 31) / 32, 4, 6), tb>>>(feat0, tf, HW0);
    transpose_feat_kernel<<<dim3((HW1 + 31) / 32, 4, 6), tb>>>(feat1, tf + (size_t)HW0 * NCAM * 128, HW1);
    transpose_feat_kernel<<<dim3((HW2 + 31) / 32, 4, 6), tb>>>(feat2, tf + (size_t)(HW0 + HW1) * NCAM * 128, HW2);
    transpose_feat_kernel<<<dim3((HW3 + 31) / 32, 4, 6), tb>>>(feat3, tf + (size_t)(HW0 + HW1 + HW2) * NCAM * 128, HW3);

    round_tf32_kernel<<<(1024 * 512 + 255) / 256, 256>>>(cw1, w1, 1024 * 512);
    round_tf32_kernel<<<(512 * 512 + 255) / 256, 256>>>(cw2, w2, 512 * 512);
    round_tf32_kernel<<<(512 * 512 + 255) / 256, 256>>>(cw3, w3, 512 * 512);
    round_tf32_kernel<<<(512 * 128 + 255) / 256, 256>>>(cw4, w4, 512 * 128);

    sample_kernel<<<QN, 128>>>(query, qpos, l2i, Wsw, bsw);

    // fvec = rna(sampled + pos_emb)
    pe_gemm<<<QN * 8 / 128, 256>>>(qpos, pew1, peb1, pew2, peb2, fv);

    const int MB = (QN + 127) / 128; // 313
    mma_gemm4<1, 1><<<dim3(4, MB), 128, dsmem>>>(fv, w1, cb1, h1, QN, 1024, 512);
    mma_gemm4<1, 1><<<dim3(4, MB), 128, dsmem>>>(h1, w2, cb2, h2, QN, 512, 512);
    mma_gemm4<1, 1><<<dim3(4, MB), 128, dsmem>>>(h2, w3, cb3, h1, QN, 512, 512);
    mma_gemm4<0, 0><<<dim3(1, MB), 128, dsmem>>>(h1, w4, cb4, h2, QN, 512, 128);

    transpose_out_kernel<<<dim3(QN / 32, 4), tb>>>(h2, out);
}